// round 14
// baseline (speedup 1.0000x reference)
#include <cuda_runtime.h>
#include <cstdint>

// BinCat: idx = sum_j (1 - x[b,i,j]) * 2^(19-j), out[row,:] = cats[idx,:]
// x:    (4096, 16, 20) int32 (0/1)   -> 65536 rows of 80 B (16B-aligned)
// cats: (2^20, 64) float32           -> 256 B rows
// out:  (4096, 16, 64) float32
//
// R14: one maximal burst per warp — 16 rows/warp, single round.
//   Evidence: all prior structures converge at ~8.5-8.9us / ~2.5TB/s,
//   duration == read-traffic / drain-rate => near the random-256B DRAM
//   activation ceiling. Only remaining lever: denser request bursts and
//   fewer serialized latency waits per row.
//     * lanes 0..15 each load one row's x (5 independent int4s) -> all
//       10 x-row loads of the warp's 16 rows in flight simultaneously
//     * compute all 16 indices, broadcast via shfl
//     * issue ALL 16 gather loads back-to-back: 32 lines in flight/warp
//     * store all 16 rows (plain stores: stay dirty in L2, writeback lazy)
//   4096 warps, 128-thread blocks -> 1024 CTAs (good wave balance).

static constexpr int LENGTH        = 20;
static constexpr int DIM           = 64;
static constexpr int ROWS_PER_WARP = 16;

__global__ void __launch_bounds__(128)
bincat_gather_kernel(const int* __restrict__ x,
                     const float* __restrict__ cats,
                     float* __restrict__ out,
                     int nrows)
{
    const int gtid     = blockIdx.x * blockDim.x + threadIdx.x;
    const int warp_id  = gtid >> 5;
    const int lane     = threadIdx.x & 31;
    const int row_base = warp_id * ROWS_PER_WARP;
    if (row_base >= nrows) return;

    // ---- Phase 1: lanes 0..15 each compute one row index ----
    // All 16 rows' x-loads (5 int4 each, independent) issue together.
    unsigned idx = 0u;
    if (lane < ROWS_PER_WARP) {
        const int myrow = row_base + lane;
        if (myrow < nrows) {
            const int4* __restrict__ xr =
                reinterpret_cast<const int4*>(x + (size_t)myrow * LENGTH);
            const int4 a0 = __ldg(&xr[0]);
            const int4 a1 = __ldg(&xr[1]);
            const int4 a2 = __ldg(&xr[2]);
            const int4 a3 = __ldg(&xr[3]);
            const int4 a4 = __ldg(&xr[4]);
            const int v[LENGTH] = { a0.x, a0.y, a0.z, a0.w,
                                    a1.x, a1.y, a1.z, a1.w,
                                    a2.x, a2.y, a2.z, a2.w,
                                    a3.x, a3.y, a3.z, a3.w,
                                    a4.x, a4.y, a4.z, a4.w };
            #pragma unroll
            for (int j = 0; j < LENGTH; ++j)
                idx |= (unsigned)(1 - v[j]) << (LENGTH - 1 - j);
        }
    }

    // ---- Phase 2a: broadcast all 16 indices ----
    unsigned ridx[ROWS_PER_WARP];
    #pragma unroll
    for (int i = 0; i < ROWS_PER_WARP; ++i)
        ridx[i] = __shfl_sync(0xffffffffu, idx, i);

    // ---- Phase 2b: issue ALL 16 gather loads (32 lines in flight) ----
    float2 v[ROWS_PER_WARP];
    #pragma unroll
    for (int i = 0; i < ROWS_PER_WARP; ++i) {
        const float2* __restrict__ src =
            reinterpret_cast<const float2*>(cats + (size_t)ridx[i] * DIM);
        v[i] = __ldg(&src[lane]);
    }

    // ---- Phase 2c: store all 16 rows (coalesced; dirty lines sit in L2) ----
    #pragma unroll
    for (int i = 0; i < ROWS_PER_WARP; ++i) {
        const int r = row_base + i;
        if (r < nrows) {
            float2* __restrict__ dst =
                reinterpret_cast<float2*>(out + (size_t)r * DIM);
            dst[lane] = v[i];
        }
    }
}

extern "C" void kernel_launch(void* const* d_in, const int* in_sizes, int n_in,
                              void* d_out, int out_size)
{
    const int*   x    = (const int*)d_in[0];    // (B, I, 20) int32
    const float* cats = (const float*)d_in[1];  // (2^20, 64) float32
    float*       out  = (float*)d_out;          // (B, I, 64) float32

    const int nrows = in_sizes[0] / LENGTH;     // 65536

    const int threads = 128;                                   // 4 warps
    const int rows_per_block = (threads / 32) * ROWS_PER_WARP; // 64 rows
    const int blocks = (nrows + rows_per_block - 1) / rows_per_block; // 1024

    bincat_gather_kernel<<<blocks, threads>>>(x, cats, out, nrows);
}

// round 15
// speedup vs baseline: 1.1479x; 1.1479x over previous
#include <cuda_runtime.h>
#include <cstdint>

// BinCat: idx = sum_j (1 - x[b,i,j]) * 2^(19-j), out[row,:] = cats[idx,:]
// x:    (4096, 16, 20) int32 (0/1)   -> 65536 rows of 80 B (16B-aligned)
// cats: (2^20, 64) float32           -> 256 B rows
// out:  (4096, 16, 64) float32
//
// R15: 4 rows/warp, float4-paired gather — minimal per-replay tail.
//   Timed (graph-replay) perf tracks tail-shortness + occupancy, not the
//   isolated ncu number (R14: ncu 8.38 but timed 11.42 at occ 37%).
//   So: shallow per-warp work, many warps.
//     * lanes 0..3 compute the 4 row indices (5 independent int4 each)
//     * pair scheme: lanes 0-15 = even row, 16-31 = odd row of each pair;
//       one LDG.128 covers 2 rows -> 2 gather loads/lane for all 4 rows
//     * plain stores (dirty lines park in L2; next replay overwrites them
//       -> avoids per-replay DRAM writeback that .cs forces)
//   16384 warps / 2048 CTAs: chip-wide in-flight lines match R4 with half
//   the per-warp depth and ~11 mem instructions per warp.

static constexpr int LENGTH        = 20;
static constexpr int DIM           = 64;
static constexpr int ROWS_PER_WARP = 4;
static constexpr int PAIRS         = ROWS_PER_WARP / 2;   // 2
static constexpr int F4_PER_ROW    = DIM / 4;             // 16

__global__ void __launch_bounds__(256)
bincat_gather_kernel(const int* __restrict__ x,
                     const float* __restrict__ cats,
                     float* __restrict__ out,
                     int nrows)
{
    const int gtid     = blockIdx.x * blockDim.x + threadIdx.x;
    const int warp_id  = gtid >> 5;
    const int lane     = threadIdx.x & 31;
    const int row_base = warp_id * ROWS_PER_WARP;
    if (row_base >= nrows) return;

    // ---- Phase 1: lanes 0..3 compute the 4 indices ----
    unsigned idx = 0u;
    if (lane < ROWS_PER_WARP) {
        const int myrow = row_base + lane;
        if (myrow < nrows) {
            const int4* __restrict__ xr =
                reinterpret_cast<const int4*>(x + (size_t)myrow * LENGTH);
            const int4 a0 = __ldg(&xr[0]);
            const int4 a1 = __ldg(&xr[1]);
            const int4 a2 = __ldg(&xr[2]);
            const int4 a3 = __ldg(&xr[3]);
            const int4 a4 = __ldg(&xr[4]);
            const int v[LENGTH] = { a0.x, a0.y, a0.z, a0.w,
                                    a1.x, a1.y, a1.z, a1.w,
                                    a2.x, a2.y, a2.z, a2.w,
                                    a3.x, a3.y, a3.z, a3.w,
                                    a4.x, a4.y, a4.z, a4.w };
            #pragma unroll
            for (int j = 0; j < LENGTH; ++j)
                idx |= (unsigned)(1 - v[j]) << (LENGTH - 1 - j);
        }
    }

    // ---- Phase 2: paired float4 gather ----
    const int half = lane >> 4;        // 0: even row of pair, 1: odd row
    const int col  = lane & 15;        // float4 column within the row

    const float4* __restrict__ cats4 = reinterpret_cast<const float4*>(cats);
    float4*       __restrict__ out4  = reinterpret_cast<float4*>(out);

    unsigned ridx[PAIRS];
    int      rrow[PAIRS];
    #pragma unroll
    for (int p = 0; p < PAIRS; ++p) {
        const int r = row_base + 2 * p + half;
        rrow[p] = r;
        ridx[p] = __shfl_sync(0xffffffffu, idx, 2 * p + half);
    }

    float4 v[PAIRS];
    #pragma unroll
    for (int p = 0; p < PAIRS; ++p)
        v[p] = __ldg(&cats4[(size_t)ridx[p] * F4_PER_ROW + col]);

    #pragma unroll
    for (int p = 0; p < PAIRS; ++p) {
        if (rrow[p] < nrows)
            out4[(size_t)rrow[p] * F4_PER_ROW + col] = v[p];
    }
}

extern "C" void kernel_launch(void* const* d_in, const int* in_sizes, int n_in,
                              void* d_out, int out_size)
{
    const int*   x    = (const int*)d_in[0];    // (B, I, 20) int32
    const float* cats = (const float*)d_in[1];  // (2^20, 64) float32
    float*       out  = (float*)d_out;          // (B, I, 64) float32

    const int nrows = in_sizes[0] / LENGTH;     // 65536

    const int threads = 256;                                   // 8 warps
    const int rows_per_block = (threads / 32) * ROWS_PER_WARP; // 32 rows
    const int blocks = (nrows + rows_per_block - 1) / rows_per_block; // 2048

    bincat_gather_kernel<<<blocks, threads>>>(x, cats, out, nrows);
}

// round 16
// speedup vs baseline: 1.3125x; 1.1434x over previous
#include <cuda_runtime.h>
#include <cstdint>

// BinCat: idx = sum_j (1 - x[b,i,j]) * 2^(19-j), out[row,:] = cats[idx,:]
// x:    (4096, 16, 20) int32 (0/1)   -> 65536 rows of 80 B (16B-aligned)
// cats: (2^20, 64) float32           -> 256 B rows (256B-aligned)
// out:  (4096, 16, 64) float32
//
// R16 = best load structure (R13) + best store policy (R4).
//   Rows-per-warp sweep: 1->11.9, 4->9.95, 8->8.70, 16->11.4, 32->13.0
//     => 8 rows/warp optimal.
//   Loads: 256-bit lanes (LDG.256, .L2::evict_last — the only legal width
//     for the hint). Warp covers 4 rows per instruction; 8 rows in 2 loads.
//     Best cold time of any variant (ncu 8.48).
//   Stores: PLAIN STG.256. Evidence: .cs stores cost ~0.2-0.25us timed
//     (R9 8.93, R13 8.90 vs R4 8.70) — evict-first forces per-replay DRAM
//     writeback; plain dirty lines park in L2 and get overwritten by the
//     next graph replay.
//   x loads: plain __ldg (R4's choice).

static constexpr int LENGTH        = 20;
static constexpr int DIM           = 64;   // 256 B per row
static constexpr int ROWS_PER_WARP = 8;

__device__ __forceinline__ void ldg_el_256(const void* p,
                                           unsigned long long r[4])
{
    asm volatile("ld.global.nc.L2::evict_last.v4.b64 {%0,%1,%2,%3}, [%4];"
                 : "=l"(r[0]), "=l"(r[1]), "=l"(r[2]), "=l"(r[3])
                 : "l"(p));
}

__device__ __forceinline__ void stg_256(void* p,
                                        const unsigned long long r[4])
{
    asm volatile("st.global.v4.b64 [%0], {%1,%2,%3,%4};"
                 :: "l"(p), "l"(r[0]), "l"(r[1]), "l"(r[2]), "l"(r[3])
                 : "memory");
}

__global__ void __launch_bounds__(256)
bincat_gather_kernel(const int* __restrict__ x,
                     const float* __restrict__ cats,
                     float* __restrict__ out,
                     int nrows)
{
    const int gtid     = blockIdx.x * blockDim.x + threadIdx.x;
    const int warp_id  = gtid >> 5;
    const int lane     = threadIdx.x & 31;
    const int row_base = warp_id * ROWS_PER_WARP;
    if (row_base >= nrows) return;

    // ---- Phase 1: lanes 0..7 compute indices (rows are 80 B = 5 x int4) ----
    unsigned idx = 0u;
    if (lane < ROWS_PER_WARP) {
        const int myrow = row_base + lane;
        if (myrow < nrows) {
            const int4* __restrict__ xr =
                reinterpret_cast<const int4*>(x + (size_t)myrow * LENGTH);
            const int4 a0 = __ldg(&xr[0]);
            const int4 a1 = __ldg(&xr[1]);
            const int4 a2 = __ldg(&xr[2]);
            const int4 a3 = __ldg(&xr[3]);
            const int4 a4 = __ldg(&xr[4]);
            const int v[LENGTH] = { a0.x, a0.y, a0.z, a0.w,
                                    a1.x, a1.y, a1.z, a1.w,
                                    a2.x, a2.y, a2.z, a2.w,
                                    a3.x, a3.y, a3.z, a3.w,
                                    a4.x, a4.y, a4.z, a4.w };
            #pragma unroll
            for (int j = 0; j < LENGTH; ++j)
                idx |= (unsigned)(1 - v[j]) << (LENGTH - 1 - j);
        }
    }

    // ---- Phase 2: 256-bit cooperative gather ----
    // Lane l handles row (row_base + 4*g + (l>>3)), byte chunk (l&7)*32.
    const int sub   = lane >> 3;        // 0..3: row within group of 4
    const int chunk = lane & 7;         // 0..7: 32B chunk within 256B row

    unsigned long long v0[4], v1[4];
    int r0, r1;
    {   // group 0: rows row_base + 0..3
        const unsigned ridx = __shfl_sync(0xffffffffu, idx, sub);
        r0 = row_base + sub;
        const char* src = reinterpret_cast<const char*>(cats)
                        + ((size_t)ridx * 256u) + (size_t)chunk * 32u;
        ldg_el_256(src, v0);
    }
    {   // group 1: rows row_base + 4..7
        const unsigned ridx = __shfl_sync(0xffffffffu, idx, 4 + sub);
        r1 = row_base + 4 + sub;
        const char* src = reinterpret_cast<const char*>(cats)
                        + ((size_t)ridx * 256u) + (size_t)chunk * 32u;
        ldg_el_256(src, v1);
    }

    // ---- stores: plain 256-bit (dirty lines park in L2 across replays) ----
    if (r0 < nrows) {
        char* dst = reinterpret_cast<char*>(out)
                  + (size_t)r0 * 256u + (size_t)chunk * 32u;
        stg_256(dst, v0);
    }
    if (r1 < nrows) {
        char* dst = reinterpret_cast<char*>(out)
                  + (size_t)r1 * 256u + (size_t)chunk * 32u;
        stg_256(dst, v1);
    }
}

extern "C" void kernel_launch(void* const* d_in, const int* in_sizes, int n_in,
                              void* d_out, int out_size)
{
    const int*   x    = (const int*)d_in[0];    // (B, I, 20) int32
    const float* cats = (const float*)d_in[1];  // (2^20, 64) float32
    float*       out  = (float*)d_out;          // (B, I, 64) float32

    const int nrows = in_sizes[0] / LENGTH;     // 65536

    const int threads = 256;                                   // 8 warps
    const int rows_per_block = (threads / 32) * ROWS_PER_WARP; // 64 rows
    const int blocks = (nrows + rows_per_block - 1) / rows_per_block; // 1024

    bincat_gather_kernel<<<blocks, threads>>>(x, cats, out, nrows);
}